// round 7
// baseline (speedup 1.0000x reference)
#include <cuda_runtime.h>
#include <cstdint>

// Problem shapes (fixed by the dataset)
#define NMAX 100000
#define EMAX 600000
#define HDIM 128
#define GMAXX 512
#define SCAN_BLK 2048          // 256 threads x 8 elems

#define LDA 132                // A-tile smem stride (pad 4: conflict-free A frags)
#define LDW 136                // W-tile smem stride (pad 8: conflict-free B frags)

// Scratch (allocation-free rule: __device__ globals)
__device__ float g_buf1[(size_t)NMAX * HDIM];   // GEMM outputs
__device__ float g_buf2[(size_t)NMAX * HDIM];   // hidden after layer 1
__device__ int   g_ideg[NMAX];                  // in-degree (excl. self loop)
__device__ float g_dis[NMAX];                   // rsqrt(deg+1)
__device__ int   g_src[EMAX];
__device__ int   g_dst[EMAX];
__device__ int   g_rowptr[NMAX + 1];
__device__ int   g_cursor[NMAX];
__device__ int   g_csr_src[EMAX];
__device__ float g_csr_nrm[EMAX];
__device__ int   g_run[128];                    // lookback running sums
__device__ int   g_flag[128];                   // lookback ready flags
__device__ float g_pool[(size_t)GMAXX * HDIM];
__device__ float g_cnt[GMAXX];

// ---------------------------------------------------------------------------
__global__ void k_init(int N, int G) {
    int i = blockIdx.x * blockDim.x + threadIdx.x;
    if (i < N) g_ideg[i] = 0;
    if (i < G * HDIM) g_pool[i] = 0.0f;
    if (i < G) g_cnt[i] = 0.0f;
    if (i < 128) g_flag[i] = 0;
}

// copy edges (int32 per harness metadata), accumulate integer in-degree
__global__ void k_edges(const int* __restrict__ ei, int E) {
    int i = blockIdx.x * blockDim.x + threadIdx.x;
    if (i >= E) return;
    int s = ei[i];
    int d = ei[(size_t)E + i];
    g_src[i] = s;
    g_dst[i] = d;
    atomicAdd(&g_ideg[d], 1);
}

// ---- single-pass exclusive scan of g_ideg -> g_rowptr (decoupled lookback) ----
__global__ void k_scan(const int* __restrict__ batch, int N, int E) {
    int b = blockIdx.x, t = threadIdx.x;
    int base = b * SCAN_BLK + t * 8;
    int pre[8];
    int s = 0;
#pragma unroll
    for (int j = 0; j < 8; j++) {
        int i = base + j;
        int v = (i < N) ? g_ideg[i] : 0;
        pre[j] = s; s += v;
    }
    int lane = t & 31, w = t >> 5;
    int incl = s;
#pragma unroll
    for (int o = 1; o < 32; o <<= 1) {
        int x = __shfl_up_sync(0xffffffffu, incl, o);
        if (lane >= o) incl += x;
    }
    __shared__ int wt[8], wb[8];
    __shared__ int sh_excl;
    if (lane == 31) wt[w] = incl;
    __syncthreads();
    if (t == 0) {
        int acc = 0;
        for (int i = 0; i < 8; i++) { wb[i] = acc; acc += wt[i]; }
        // lookback chain: wait for predecessor's running total
        int excl = 0;
        if (b > 0) {
            while (atomicAdd(&g_flag[b - 1], 0) == 0) { }
            __threadfence();
            excl = g_run[b - 1];
        }
        g_run[b] = excl + acc;
        __threadfence();
        atomicExch(&g_flag[b], 1);
        sh_excl = excl;
    }
    __syncthreads();
    int gbase = sh_excl + wb[w] + (incl - s);
#pragma unroll
    for (int j = 0; j < 8; j++) {
        int i = base + j;
        if (i < N) {
            int rp = gbase + pre[j];
            g_rowptr[i] = rp;
            g_cursor[i] = rp;
            g_dis[i] = rsqrtf((float)(g_ideg[i] + 1));
            atomicAdd(&g_cnt[batch[i]], 1.0f);
        }
    }
    if (b == 0 && t == 0) g_rowptr[N] = E;
}

// fill CSR buckets (norm computed here; reused by both layers)
__global__ void k_fill(int E) {
    int e = blockIdx.x * blockDim.x + threadIdx.x;
    if (e >= E) return;
    int s = g_src[e], d = g_dst[e];
    int pos = atomicAdd(&g_cursor[d], 1);
    g_csr_src[pos] = s;
    g_csr_nrm[pos] = g_dis[s] * g_dis[d];
}

// ---------------------------------------------------------------------------
// 3xTF32 GEMM: C[N,128] = A[N,128] @ W[128,128], fp32-grade accuracy.
__device__ __forceinline__ uint32_t f2tf32(float x) {
    uint32_t r;
    asm("cvt.rna.tf32.f32 %0, %1;" : "=r"(r) : "f"(x));
    return r;
}
__device__ __forceinline__ void split_tf32(float x, uint32_t& hi, uint32_t& lo) {
    hi = f2tf32(x);
    lo = f2tf32(x - __uint_as_float(hi));
}
__device__ __forceinline__ void mma_tf32(float* c, const uint32_t* a, const uint32_t* b) {
    asm volatile(
        "mma.sync.aligned.m16n8k8.row.col.f32.tf32.tf32.f32 "
        "{%0,%1,%2,%3}, {%4,%5,%6,%7}, {%8,%9}, {%0,%1,%2,%3};"
        : "+f"(c[0]), "+f"(c[1]), "+f"(c[2]), "+f"(c[3])
        : "r"(a[0]), "r"(a[1]), "r"(a[2]), "r"(a[3]), "r"(b[0]), "r"(b[1]));
}

__global__ void k_gemm_tf32(const float* __restrict__ A, const float* __restrict__ Wm,
                            float* __restrict__ C, int N) {
    extern __shared__ float sh[];
    float* sW = sh;                   // 128 x LDW
    float* sA = sh + 128 * LDW;       // 128 x LDA
    int tid = threadIdx.x;
    int row0 = blockIdx.x * 128;

    const float4* W4 = (const float4*)Wm;
    const float4* A4 = (const float4*)A;
#pragma unroll
    for (int i = 0; i < 16; i++) {
        int idx = tid + 256 * i;       // 0..4095
        int r = idx >> 5;              // 0..127
        int c4 = idx & 31;
        *(float4*)&sW[r * LDW + c4 * 4] = W4[idx];
        float4 v = make_float4(0.f, 0.f, 0.f, 0.f);
        if (row0 + r < N) v = A4[(size_t)(row0 + r) * 32 + c4];
        *(float4*)&sA[r * LDA + c4 * 4] = v;
    }
    __syncthreads();

    int wid = tid >> 5, lane = tid & 31;
    int gid = lane >> 2, tig = lane & 3;
    int mbase = (wid >> 2) * 64;       // warp_m in {0,1}
    int nbase = (wid & 3) * 32;        // warp_n in {0..3}

    float acc[4][4][4];
#pragma unroll
    for (int i = 0; i < 4; i++)
#pragma unroll
        for (int j = 0; j < 4; j++)
#pragma unroll
            for (int r = 0; r < 4; r++) acc[i][j][r] = 0.f;

#pragma unroll
    for (int kt = 0; kt < 16; kt++) {
        int k0 = kt * 8;
        uint32_t bh[4][2], bl[4][2];
#pragma unroll
        for (int nt = 0; nt < 4; nt++) {
            int ncol = nbase + nt * 8 + gid;
            float b0f = sW[(k0 + tig) * LDW + ncol];
            float b1f = sW[(k0 + tig + 4) * LDW + ncol];
            split_tf32(b0f, bh[nt][0], bl[nt][0]);
            split_tf32(b1f, bh[nt][1], bl[nt][1]);
        }
#pragma unroll
        for (int mt = 0; mt < 4; mt++) {
            int r0 = mbase + mt * 16 + gid;
            float a0f = sA[r0 * LDA + k0 + tig];
            float a1f = sA[(r0 + 8) * LDA + k0 + tig];
            float a2f = sA[r0 * LDA + k0 + tig + 4];
            float a3f = sA[(r0 + 8) * LDA + k0 + tig + 4];
            uint32_t ah[4], al[4];
            split_tf32(a0f, ah[0], al[0]);
            split_tf32(a1f, ah[1], al[1]);
            split_tf32(a2f, ah[2], al[2]);
            split_tf32(a3f, ah[3], al[3]);
#pragma unroll
            for (int nt = 0; nt < 4; nt++) {
                mma_tf32(acc[mt][nt], ah, bh[nt]);
                mma_tf32(acc[mt][nt], ah, bl[nt]);
                mma_tf32(acc[mt][nt], al, bh[nt]);
            }
        }
    }

#pragma unroll
    for (int mt = 0; mt < 4; mt++) {
#pragma unroll
        for (int nt = 0; nt < 4; nt++) {
            int r = row0 + mbase + mt * 16 + gid;
            int c = nbase + nt * 8 + 2 * tig;
            if (r < N)
                *(float2*)&C[(size_t)r * 128 + c] =
                    make_float2(acc[mt][nt][0], acc[mt][nt][1]);
            if (r + 8 < N)
                *(float2*)&C[(size_t)(r + 8) * 128 + c] =
                    make_float2(acc[mt][nt][2], acc[mt][nt][3]);
        }
    }
}

// ---------------------------------------------------------------------------
// Gather-side aggregation (atomic-free): one warp per node, MLP-4 edge loop.
template <int POOL>
__global__ void k_agg(const float* __restrict__ gm, const float* __restrict__ bias,
                      float* __restrict__ outb, const int* __restrict__ batch, int N) {
    int n = (blockIdx.x * blockDim.x + threadIdx.x) >> 5;
    int lane = threadIdx.x & 31;
    if (n >= N) return;

    float selfw = g_dis[n];
    selfw *= selfw;
    const float4* gm4 = (const float4*)gm;
    float4 acc = gm4[(size_t)n * 32 + lane];
    acc.x *= selfw; acc.y *= selfw; acc.z *= selfw; acc.w *= selfw;

    int beg = g_rowptr[n], end = g_rowptr[n + 1];
    int e = beg;
    for (; e + 4 <= end; e += 4) {
        int s0 = g_csr_src[e + 0], s1 = g_csr_src[e + 1];
        int s2 = g_csr_src[e + 2], s3 = g_csr_src[e + 3];
        float w0 = g_csr_nrm[e + 0], w1 = g_csr_nrm[e + 1];
        float w2 = g_csr_nrm[e + 2], w3 = g_csr_nrm[e + 3];
        float4 v0 = gm4[(size_t)s0 * 32 + lane];
        float4 v1 = gm4[(size_t)s1 * 32 + lane];
        float4 v2 = gm4[(size_t)s2 * 32 + lane];
        float4 v3 = gm4[(size_t)s3 * 32 + lane];
        acc.x += v0.x * w0 + v1.x * w1 + v2.x * w2 + v3.x * w3;
        acc.y += v0.y * w0 + v1.y * w1 + v2.y * w2 + v3.y * w3;
        acc.z += v0.z * w0 + v1.z * w1 + v2.z * w2 + v3.z * w3;
        acc.w += v0.w * w0 + v1.w * w1 + v2.w * w2 + v3.w * w3;
    }
    for (; e < end; e++) {
        int s = g_csr_src[e];
        float wn = g_csr_nrm[e];
        float4 v = gm4[(size_t)s * 32 + lane];
        acc.x += v.x * wn;
        acc.y += v.y * wn;
        acc.z += v.z * wn;
        acc.w += v.w * wn;
    }

    float4 b = ((const float4*)bias)[lane];
    acc.x = fmaxf(acc.x + b.x, 0.f);
    acc.y = fmaxf(acc.y + b.y, 0.f);
    acc.z = fmaxf(acc.z + b.z, 0.f);
    acc.w = fmaxf(acc.w + b.w, 0.f);

    if (POOL) {
        int g = batch[n];
        float* p = g_pool + (size_t)g * 128 + lane * 4;
        atomicAdd(p + 0, acc.x);
        atomicAdd(p + 1, acc.y);
        atomicAdd(p + 2, acc.z);
        atomicAdd(p + 3, acc.w);
    } else {
        ((float4*)outb)[(size_t)n * 32 + lane] = acc;
    }
}

// final: out[g] = (pool[g]/cnt[g]) . Wfc + bfc
__global__ void k_final(const float* __restrict__ Wfc, const float* __restrict__ bfc,
                        float* __restrict__ out, int G) {
    int g = blockIdx.x;
    int t = threadIdx.x;           // 128 threads
    float c = fmaxf(g_cnt[g], 1.0f);
    float val = (g_pool[(size_t)g * 128 + t] / c) * Wfc[t];
#pragma unroll
    for (int o = 16; o > 0; o >>= 1) val += __shfl_down_sync(0xffffffffu, val, o);
    __shared__ float sred[4];
    int w = t >> 5;
    if ((t & 31) == 0) sred[w] = val;
    __syncthreads();
    if (t == 0) out[g] = sred[0] + sred[1] + sred[2] + sred[3] + bfc[0];
}

// ---------------------------------------------------------------------------
extern "C" void kernel_launch(void* const* d_in, const int* in_sizes, int n_in,
                              void* d_out, int out_size) {
    const float* x     = (const float*)d_in[0];
    const int*   ei    = (const int*)d_in[1];    // int32 in harness
    const int*   batch = (const int*)d_in[2];    // int32 in harness
    const float* W1    = (const float*)d_in[3];
    const float* b1    = (const float*)d_in[4];
    const float* W2    = (const float*)d_in[5];
    const float* b2    = (const float*)d_in[6];
    const float* Wfc   = (const float*)d_in[7];
    const float* bfc   = (const float*)d_in[8];
    float* out = (float*)d_out;

    int N = in_sizes[0] / HDIM;
    int E = in_sizes[1] / 2;
    int G = out_size;

    float *buf1, *buf2;
    cudaGetSymbolAddress((void**)&buf1, g_buf1);
    cudaGetSymbolAddress((void**)&buf2, g_buf2);

    size_t gsmem = (size_t)(128 * LDW + 128 * LDA) * sizeof(float);   // ~137 KB
    cudaFuncSetAttribute(k_gemm_tf32, cudaFuncAttributeMaxDynamicSharedMemorySize,
                         (int)gsmem);

    int initN = N > G * HDIM ? N : G * HDIM;
    int nblk = (N + SCAN_BLK - 1) / SCAN_BLK;

    int gemmGrid = (N + 127) / 128;
    int aggBlocks = (N * 32 + 255) / 256;

    // Launch order note: the profiler snapshots the 4th launch -> put the
    // layer-1 GEMM there (it only depends on inputs; prep chain is independent).
    k_init<<<(initN + 255) / 256, 256>>>(N, G);                 // 1
    k_edges<<<(E + 255) / 256, 256>>>(ei, E);                   // 2
    k_scan<<<nblk, 256>>>(batch, N, E);                         // 3
    k_gemm_tf32<<<gemmGrid, 256, gsmem>>>(x, W1, buf1, N);      // 4  <- profiled
    k_fill<<<(E + 255) / 256, 256>>>(E);                        // 5

    // ---- layer 1 aggregation ----
    k_agg<0><<<aggBlocks, 256>>>(buf1, b1, buf2, batch, N);     // 6

    // ---- layer 2 (pool fused into aggregation epilogue) ----
    k_gemm_tf32<<<gemmGrid, 256, gsmem>>>(buf2, W2, buf1, N);   // 7
    k_agg<1><<<aggBlocks, 256>>>(buf1, b2, nullptr, batch, N);  // 8

    // ---- readout ----
    k_final<<<G, 128>>>(Wfc, bfc, out, G);                      // 9
}

// round 12
// speedup vs baseline: 1.2332x; 1.2332x over previous
#include <cuda_runtime.h>
#include <cstdint>

// Problem shapes (fixed by the dataset)
#define NMAX 100000
#define EMAX 600000
#define HDIM 128
#define GMAXX 512
#define SCAN_BLK 2048          // 256 threads x 8 elems

#define LDA 132                // A-tile smem stride (pad 4: conflict-free A frags)
#define LDW 136                // W-tile smem stride (pad 8: conflict-free B frags)
#define MBLK 64                // GEMM rows per block (smaller tile -> 2 blocks/SM)

// Scratch (allocation-free rule: __device__ globals)
__device__ float g_buf1[(size_t)NMAX * HDIM];   // GEMM outputs
__device__ float g_buf2[(size_t)NMAX * HDIM];   // hidden after layer 1
__device__ int   g_ideg[NMAX];                  // in-degree (excl. self loop)
__device__ float g_dis[NMAX];                   // rsqrt(deg+1)
__device__ int   g_src[EMAX];
__device__ int   g_dst[EMAX];
__device__ int   g_rowptr[NMAX + 1];
__device__ int   g_cursor[NMAX];
__device__ int   g_csr_src[EMAX];
__device__ float g_csr_nrm[EMAX];
__device__ int   g_blk[128];                    // scan block sums
__device__ float g_pool[(size_t)GMAXX * HDIM];
__device__ float g_cnt[GMAXX];

// ---------------------------------------------------------------------------
__global__ void k_init(int N, int G) {
    int i = blockIdx.x * blockDim.x + threadIdx.x;
    if (i < N) g_ideg[i] = 0;
    if (i < G * HDIM) g_pool[i] = 0.0f;
    if (i < G) g_cnt[i] = 0.0f;
}

// copy edges (int32 per harness metadata), accumulate integer in-degree
__global__ void k_edges(const int* __restrict__ ei, int E) {
    int i = blockIdx.x * blockDim.x + threadIdx.x;
    if (i >= E) return;
    int s = ei[i];
    int d = ei[(size_t)E + i];
    g_src[i] = s;
    g_dst[i] = d;
    atomicAdd(&g_ideg[d], 1);
}

// ---- exclusive scan of g_ideg -> g_rowptr (2 kernels, no spin chains) ----
__global__ void k_scan_a(int N) {           // per-block sums
    int b = blockIdx.x, t = threadIdx.x;
    int base = b * SCAN_BLK + t * 8;
    int s = 0;
#pragma unroll
    for (int j = 0; j < 8; j++) { int i = base + j; s += (i < N) ? g_ideg[i] : 0; }
#pragma unroll
    for (int o = 16; o > 0; o >>= 1) s += __shfl_down_sync(0xffffffffu, s, o);
    __shared__ int wt[8];
    if ((t & 31) == 0) wt[t >> 5] = s;
    __syncthreads();
    if (t == 0) {
        int acc = 0;
        for (int i = 0; i < 8; i++) acc += wt[i];
        g_blk[b] = acc;
    }
}

__global__ void k_scan_c(const int* __restrict__ batch, int N, int E) {
    int b = blockIdx.x, t = threadIdx.x;
    __shared__ int blkoff;
    if (t == 0) {                       // per-block serial prefix over <=49 blocks
        int acc = 0;
        for (int i = 0; i < b; i++) acc += g_blk[i];
        blkoff = acc;
    }
    int base = b * SCAN_BLK + t * 8;
    int pre[8];
    int s = 0;
#pragma unroll
    for (int j = 0; j < 8; j++) {
        int i = base + j;
        int v = (i < N) ? g_ideg[i] : 0;
        pre[j] = s; s += v;
    }
    int lane = t & 31, w = t >> 5;
    int incl = s;
#pragma unroll
    for (int o = 1; o < 32; o <<= 1) {
        int x = __shfl_up_sync(0xffffffffu, incl, o);
        if (lane >= o) incl += x;
    }
    __shared__ int wt[8], wb[8];
    if (lane == 31) wt[w] = incl;
    __syncthreads();
    if (t == 0) {
        int acc = 0;
        for (int i = 0; i < 8; i++) { wb[i] = acc; acc += wt[i]; }
    }
    __syncthreads();
    int thr_excl = wb[w] + incl - s;
    int gbase = blkoff + thr_excl;
#pragma unroll
    for (int j = 0; j < 8; j++) {
        int i = base + j;
        if (i < N) {
            int rp = gbase + pre[j];
            g_rowptr[i] = rp;
            g_cursor[i] = rp;
            g_dis[i] = rsqrtf((float)(g_ideg[i] + 1));
            atomicAdd(&g_cnt[batch[i]], 1.0f);
        }
    }
    if (b == 0 && t == 0) g_rowptr[N] = E;
}

// fill CSR buckets (norm computed here; reused by both layers)
__global__ void k_fill(int E) {
    int e = blockIdx.x * blockDim.x + threadIdx.x;
    if (e >= E) return;
    int s = g_src[e], d = g_dst[e];
    int pos = atomicAdd(&g_cursor[d], 1);
    g_csr_src[pos] = s;
    g_csr_nrm[pos] = g_dis[s] * g_dis[d];
}

// ---------------------------------------------------------------------------
// 3xTF32 GEMM: C[N,128] = A[N,128] @ W[128,128], fp32-grade accuracy.
// Block: MBLK=64 rows x 128 cols, 256 threads (8 warps 2x4, warp tile 32x32).
// Smaller M-tile halves smem (~101 KB) -> 2 blocks/SM -> 4 warps/SMSP for
// latency hiding (R7 profile: occ 12.2%, issue 36.2% at 1 block/SM).
__device__ __forceinline__ uint32_t f2tf32(float x) {
    uint32_t r;
    asm("cvt.rna.tf32.f32 %0, %1;" : "=r"(r) : "f"(x));
    return r;
}
__device__ __forceinline__ void split_tf32(float x, uint32_t& hi, uint32_t& lo) {
    hi = f2tf32(x);
    lo = f2tf32(x - __uint_as_float(hi));
}
__device__ __forceinline__ void mma_tf32(float* c, const uint32_t* a, const uint32_t* b) {
    asm volatile(
        "mma.sync.aligned.m16n8k8.row.col.f32.tf32.tf32.f32 "
        "{%0,%1,%2,%3}, {%4,%5,%6,%7}, {%8,%9}, {%0,%1,%2,%3};"
        : "+f"(c[0]), "+f"(c[1]), "+f"(c[2]), "+f"(c[3])
        : "r"(a[0]), "r"(a[1]), "r"(a[2]), "r"(a[3]), "r"(b[0]), "r"(b[1]));
}

__global__ void __launch_bounds__(256, 2)
k_gemm_tf32(const float* __restrict__ A, const float* __restrict__ Wm,
            float* __restrict__ C, int N) {
    extern __shared__ float sh[];
    float* sW = sh;                   // 128 x LDW
    float* sA = sh + 128 * LDW;       // MBLK x LDA
    int tid = threadIdx.x;
    int row0 = blockIdx.x * MBLK;

    const float4* W4 = (const float4*)Wm;
    const float4* A4 = (const float4*)A;
#pragma unroll
    for (int i = 0; i < 16; i++) {
        int idx = tid + 256 * i;       // 0..4095
        int r = idx >> 5;              // 0..127
        int c4 = idx & 31;
        *(float4*)&sW[r * LDW + c4 * 4] = W4[idx];
    }
#pragma unroll
    for (int i = 0; i < 8; i++) {
        int idx = tid + 256 * i;       // 0..2047
        int r = idx >> 5;              // 0..63
        int c4 = idx & 31;
        float4 v = make_float4(0.f, 0.f, 0.f, 0.f);
        if (row0 + r < N) v = A4[(size_t)(row0 + r) * 32 + c4];
        *(float4*)&sA[r * LDA + c4 * 4] = v;
    }
    __syncthreads();

    int wid = tid >> 5, lane = tid & 31;
    int gid = lane >> 2, tig = lane & 3;
    int mbase = (wid >> 2) * 32;       // warp_m in {0,1}
    int nbase = (wid & 3) * 32;        // warp_n in {0..3}

    float acc[2][4][4];
#pragma unroll
    for (int i = 0; i < 2; i++)
#pragma unroll
        for (int j = 0; j < 4; j++)
#pragma unroll
            for (int r = 0; r < 4; r++) acc[i][j][r] = 0.f;

#pragma unroll
    for (int kt = 0; kt < 16; kt++) {
        int k0 = kt * 8;
        uint32_t bh[4][2], bl[4][2];
#pragma unroll
        for (int nt = 0; nt < 4; nt++) {
            int ncol = nbase + nt * 8 + gid;
            float b0f = sW[(k0 + tig) * LDW + ncol];
            float b1f = sW[(k0 + tig + 4) * LDW + ncol];
            split_tf32(b0f, bh[nt][0], bl[nt][0]);
            split_tf32(b1f, bh[nt][1], bl[nt][1]);
        }
#pragma unroll
        for (int mt = 0; mt < 2; mt++) {
            int r0 = mbase + mt * 16 + gid;
            float a0f = sA[r0 * LDA + k0 + tig];
            float a1f = sA[(r0 + 8) * LDA + k0 + tig];
            float a2f = sA[r0 * LDA + k0 + tig + 4];
            float a3f = sA[(r0 + 8) * LDA + k0 + tig + 4];
            uint32_t ah[4], al[4];
            split_tf32(a0f, ah[0], al[0]);
            split_tf32(a1f, ah[1], al[1]);
            split_tf32(a2f, ah[2], al[2]);
            split_tf32(a3f, ah[3], al[3]);
#pragma unroll
            for (int nt = 0; nt < 4; nt++) {
                mma_tf32(acc[mt][nt], ah, bh[nt]);
                mma_tf32(acc[mt][nt], ah, bl[nt]);
                mma_tf32(acc[mt][nt], al, bh[nt]);
            }
        }
    }

#pragma unroll
    for (int mt = 0; mt < 2; mt++) {
#pragma unroll
        for (int nt = 0; nt < 4; nt++) {
            int r = row0 + mbase + mt * 16 + gid;
            int c = nbase + nt * 8 + 2 * tig;
            if (r < N)
                *(float2*)&C[(size_t)r * 128 + c] =
                    make_float2(acc[mt][nt][0], acc[mt][nt][1]);
            if (r + 8 < N)
                *(float2*)&C[(size_t)(r + 8) * 128 + c] =
                    make_float2(acc[mt][nt][2], acc[mt][nt][3]);
        }
    }
}

// ---------------------------------------------------------------------------
// Gather-side aggregation (atomic-free): one warp per node (simple loop).
template <int POOL>
__global__ void k_agg(const float* __restrict__ gm, const float* __restrict__ bias,
                      float* __restrict__ outb, const int* __restrict__ batch, int N) {
    int n = (blockIdx.x * blockDim.x + threadIdx.x) >> 5;
    int lane = threadIdx.x & 31;
    if (n >= N) return;

    float selfw = g_dis[n];
    selfw *= selfw;
    const float4* gm4 = (const float4*)gm;
    float4 acc = gm4[(size_t)n * 32 + lane];
    acc.x *= selfw; acc.y *= selfw; acc.z *= selfw; acc.w *= selfw;

    int beg = g_rowptr[n], end = g_rowptr[n + 1];
    for (int e = beg; e < end; e++) {
        int s = g_csr_src[e];
        float wn = g_csr_nrm[e];
        float4 v = gm4[(size_t)s * 32 + lane];
        acc.x += v.x * wn;
        acc.y += v.y * wn;
        acc.z += v.z * wn;
        acc.w += v.w * wn;
    }

    float4 b = ((const float4*)bias)[lane];
    acc.x = fmaxf(acc.x + b.x, 0.f);
    acc.y = fmaxf(acc.y + b.y, 0.f);
    acc.z = fmaxf(acc.z + b.z, 0.f);
    acc.w = fmaxf(acc.w + b.w, 0.f);

    if (POOL) {
        int g = batch[n];
        float* p = g_pool + (size_t)g * 128 + lane * 4;
        atomicAdd(p + 0, acc.x);
        atomicAdd(p + 1, acc.y);
        atomicAdd(p + 2, acc.z);
        atomicAdd(p + 3, acc.w);
    } else {
        ((float4*)outb)[(size_t)n * 32 + lane] = acc;
    }
}

// final: out[g] = (pool[g]/cnt[g]) . Wfc + bfc
__global__ void k_final(const float* __restrict__ Wfc, const float* __restrict__ bfc,
                        float* __restrict__ out, int G) {
    int g = blockIdx.x;
    int t = threadIdx.x;           // 128 threads
    float c = fmaxf(g_cnt[g], 1.0f);
    float val = (g_pool[(size_t)g * 128 + t] / c) * Wfc[t];
#pragma unroll
    for (int o = 16; o > 0; o >>= 1) val += __shfl_down_sync(0xffffffffu, val, o);
    __shared__ float sred[4];
    int w = t >> 5;
    if ((t & 31) == 0) sred[w] = val;
    __syncthreads();
    if (t == 0) out[g] = sred[0] + sred[1] + sred[2] + sred[3] + bfc[0];
}

// ---------------------------------------------------------------------------
// R10 resubmission of the R8 experiment (GEMM occupancy 1->2 blocks/SM).
// Prior two rounds died to broker-level container failures, not kernel errors.
extern "C" void kernel_launch(void* const* d_in, const int* in_sizes, int n_in,
                              void* d_out, int out_size) {
    const float* x     = (const float*)d_in[0];
    const int*   ei    = (const int*)d_in[1];    // int32 in harness
    const int*   batch = (const int*)d_in[2];    // int32 in harness
    const float* W1    = (const float*)d_in[3];
    const float* b1    = (const float*)d_in[4];
    const float* W2    = (const float*)d_in[5];
    const float* b2    = (const float*)d_in[6];
    const float* Wfc   = (const float*)d_in[7];
    const float* bfc   = (const float*)d_in[8];
    float* out = (float*)d_out;

    int N = in_sizes[0] / HDIM;
    int E = in_sizes[1] / 2;
    int G = out_size;

    float *buf1, *buf2;
    cudaGetSymbolAddress((void**)&buf1, g_buf1);
    cudaGetSymbolAddress((void**)&buf2, g_buf2);

    size_t gsmem = (size_t)(128 * LDW + MBLK * LDA) * sizeof(float);   // ~101 KB
    cudaFuncSetAttribute(k_gemm_tf32, cudaFuncAttributeMaxDynamicSharedMemorySize,
                         (int)gsmem);

    int initN = N > G * HDIM ? N : G * HDIM;
    int nblk = (N + SCAN_BLK - 1) / SCAN_BLK;

    int gemmGrid = (N + MBLK - 1) / MBLK;
    int aggBlocks = (N * 32 + 255) / 256;

    // Profiler snapshots the 4th launch -> keep layer-1 GEMM there.
    k_init<<<(initN + 255) / 256, 256>>>(N, G);                 // 1
    k_edges<<<(E + 255) / 256, 256>>>(ei, E);                   // 2
    k_scan_a<<<nblk, 256>>>(N);                                 // 3
    k_gemm_tf32<<<gemmGrid, 256, gsmem>>>(x, W1, buf1, N);      // 4  <- profiled
    k_scan_c<<<nblk, 256>>>(batch, N, E);                       // 5
    k_fill<<<(E + 255) / 256, 256>>>(E);                        // 6

    // ---- layer 1 aggregation ----
    k_agg<0><<<aggBlocks, 256>>>(buf1, b1, buf2, batch, N);     // 7

    // ---- layer 2 (pool fused into aggregation epilogue) ----
    k_gemm_tf32<<<gemmGrid, 256, gsmem>>>(buf2, W2, buf1, N);   // 8
    k_agg<1><<<aggBlocks, 256>>>(buf1, b2, nullptr, batch, N);  // 9

    // ---- readout ----
    k_final<<<G, 128>>>(Wfc, bfc, out, G);                      // 10
}

// round 14
// speedup vs baseline: 1.2568x; 1.0191x over previous
#include <cuda_runtime.h>
#include <cstdint>

// Problem shapes (fixed by the dataset)
#define NMAX 100000
#define EMAX 600000
#define HDIM 128
#define GMAXX 512
#define SCAN_BLK 2048          // 256 threads x 8 elems

#define LDA 132                // A-tile smem stride (pad 4: conflict-free A frags)
#define LDW 136                // W-tile smem stride (pad 8: conflict-free B frags)
#define MBLK 64                // GEMM rows per block (2 blocks/SM)

// Scratch (allocation-free rule: __device__ globals)
__device__ float g_buf1[(size_t)NMAX * HDIM];   // GEMM outputs
__device__ float g_buf2[(size_t)NMAX * HDIM];   // hidden after layer 1
__device__ int   g_ideg[NMAX];                  // in-degree (excl. self loop)
__device__ float g_dis[NMAX];                   // rsqrt(deg+1)
__device__ int   g_rowptr[NMAX + 1];
__device__ int   g_cursor[NMAX];
__device__ int   g_csr_src[EMAX];
__device__ float g_csr_nrm[EMAX];
__device__ int   g_blk[128];                    // scan block sums
__device__ float g_pool[(size_t)GMAXX * HDIM];
__device__ float g_cnt[GMAXX];

// ---------------------------------------------------------------------------
__global__ void k_init(int N, int G) {
    int i = blockIdx.x * blockDim.x + threadIdx.x;
    if (i < N) g_ideg[i] = 0;
    if (i < G * HDIM) g_pool[i] = 0.0f;
    if (i < G) g_cnt[i] = 0.0f;
}

// degree histogram only (src/dst live in ei; the R12 copy was pure overhead)
__global__ void k_edges(const int* __restrict__ ei, int E) {
    int i = blockIdx.x * blockDim.x + threadIdx.x;
    if (i >= E) return;
    atomicAdd(&g_ideg[ei[(size_t)E + i]], 1);
}

// ---- exclusive scan of g_ideg -> g_rowptr ----
__global__ void k_scan_a(int N) {           // per-block sums
    int b = blockIdx.x, t = threadIdx.x;
    int base = b * SCAN_BLK + t * 8;
    int s = 0;
#pragma unroll
    for (int j = 0; j < 8; j++) { int i = base + j; s += (i < N) ? g_ideg[i] : 0; }
#pragma unroll
    for (int o = 16; o > 0; o >>= 1) s += __shfl_down_sync(0xffffffffu, s, o);
    __shared__ int wt[8];
    if ((t & 31) == 0) wt[t >> 5] = s;
    __syncthreads();
    if (t == 0) {
        int acc = 0;
        for (int i = 0; i < 8; i++) acc += wt[i];
        g_blk[b] = acc;
    }
}

__global__ void k_scan_c(const int* __restrict__ batch, int N, int E, int nblk) {
    int b = blockIdx.x, t = threadIdx.x;
    // Block offset: stage all block sums into smem in parallel (1 LDG each),
    // then a short smem-resident prefix. R6 version serially read up to 48
    // GLOBAL values from thread 0 (~570cyc each) -> 19.6us kernel. This is the fix.
    __shared__ int sblk[128];
    __shared__ int blkoff;
    if (t < 128) sblk[t] = (t < nblk) ? g_blk[t] : 0;
    __syncthreads();
    if (t == 0) {
        int acc = 0;
        for (int i = 0; i < b; i++) acc += sblk[i];
        blkoff = acc;
    }
    int base = b * SCAN_BLK + t * 8;
    int pre[8];
    int s = 0;
#pragma unroll
    for (int j = 0; j < 8; j++) {
        int i = base + j;
        int v = (i < N) ? g_ideg[i] : 0;
        pre[j] = s; s += v;
    }
    int lane = t & 31, w = t >> 5;
    int incl = s;
#pragma unroll
    for (int o = 1; o < 32; o <<= 1) {
        int x = __shfl_up_sync(0xffffffffu, incl, o);
        if (lane >= o) incl += x;
    }
    __shared__ int wt[8], wb[8];
    if (lane == 31) wt[w] = incl;
    __syncthreads();
    if (t == 0) {
        int acc = 0;
        for (int i = 0; i < 8; i++) { wb[i] = acc; acc += wt[i]; }
    }
    __syncthreads();
    int thr_excl = wb[w] + incl - s;
    int gbase = blkoff + thr_excl;
#pragma unroll
    for (int j = 0; j < 8; j++) {
        int i = base + j;
        if (i < N) {
            int rp = gbase + pre[j];
            g_rowptr[i] = rp;
            g_cursor[i] = rp;
            g_dis[i] = rsqrtf((float)(g_ideg[i] + 1));
            atomicAdd(&g_cnt[batch[i]], 1.0f);
        }
    }
    if (b == 0 && t == 0) g_rowptr[N] = E;
}

// fill CSR buckets straight from ei (norm computed here; reused by both layers)
__global__ void k_fill(const int* __restrict__ ei, int E) {
    int e = blockIdx.x * blockDim.x + threadIdx.x;
    if (e >= E) return;
    int s = ei[e];
    int d = ei[(size_t)E + e];
    int pos = atomicAdd(&g_cursor[d], 1);
    g_csr_src[pos] = s;
    g_csr_nrm[pos] = g_dis[s] * g_dis[d];
}

// ---------------------------------------------------------------------------
// 3xTF32 GEMM: C[N,128] = A[N,128] @ W[128,128], fp32-grade accuracy.
__device__ __forceinline__ uint32_t f2tf32(float x) {
    uint32_t r;
    asm("cvt.rna.tf32.f32 %0, %1;" : "=r"(r) : "f"(x));
    return r;
}
__device__ __forceinline__ void split_tf32(float x, uint32_t& hi, uint32_t& lo) {
    hi = f2tf32(x);
    lo = f2tf32(x - __uint_as_float(hi));
}
__device__ __forceinline__ void mma_tf32(float* c, const uint32_t* a, const uint32_t* b) {
    asm volatile(
        "mma.sync.aligned.m16n8k8.row.col.f32.tf32.tf32.f32 "
        "{%0,%1,%2,%3}, {%4,%5,%6,%7}, {%8,%9}, {%0,%1,%2,%3};"
        : "+f"(c[0]), "+f"(c[1]), "+f"(c[2]), "+f"(c[3])
        : "r"(a[0]), "r"(a[1]), "r"(a[2]), "r"(a[3]), "r"(b[0]), "r"(b[1]));
}

__global__ void __launch_bounds__(256, 2)
k_gemm_tf32(const float* __restrict__ A, const float* __restrict__ Wm,
            float* __restrict__ C, int N) {
    extern __shared__ float sh[];
    float* sW = sh;                   // 128 x LDW
    float* sA = sh + 128 * LDW;       // MBLK x LDA
    int tid = threadIdx.x;
    int row0 = blockIdx.x * MBLK;

    const float4* W4 = (const float4*)Wm;
    const float4* A4 = (const float4*)A;
#pragma unroll
    for (int i = 0; i < 16; i++) {
        int idx = tid + 256 * i;       // 0..4095
        int r = idx >> 5;              // 0..127
        int c4 = idx & 31;
        *(float4*)&sW[r * LDW + c4 * 4] = W4[idx];
    }
#pragma unroll
    for (int i = 0; i < 8; i++) {
        int idx = tid + 256 * i;       // 0..2047
        int r = idx >> 5;              // 0..63
        int c4 = idx & 31;
        float4 v = make_float4(0.f, 0.f, 0.f, 0.f);
        if (row0 + r < N) v = A4[(size_t)(row0 + r) * 32 + c4];
        *(float4*)&sA[r * LDA + c4 * 4] = v;
    }
    __syncthreads();

    int wid = tid >> 5, lane = tid & 31;
    int gid = lane >> 2, tig = lane & 3;
    int mbase = (wid >> 2) * 32;       // warp_m in {0,1}
    int nbase = (wid & 3) * 32;        // warp_n in {0..3}

    float acc[2][4][4];
#pragma unroll
    for (int i = 0; i < 2; i++)
#pragma unroll
        for (int j = 0; j < 4; j++)
#pragma unroll
            for (int r = 0; r < 4; r++) acc[i][j][r] = 0.f;

#pragma unroll
    for (int kt = 0; kt < 16; kt++) {
        int k0 = kt * 8;
        uint32_t bh[4][2], bl[4][2];
#pragma unroll
        for (int nt = 0; nt < 4; nt++) {
            int ncol = nbase + nt * 8 + gid;
            float b0f = sW[(k0 + tig) * LDW + ncol];
            float b1f = sW[(k0 + tig + 4) * LDW + ncol];
            split_tf32(b0f, bh[nt][0], bl[nt][0]);
            split_tf32(b1f, bh[nt][1], bl[nt][1]);
        }
#pragma unroll
        for (int mt = 0; mt < 2; mt++) {
            int r0 = mbase + mt * 16 + gid;
            float a0f = sA[r0 * LDA + k0 + tig];
            float a1f = sA[(r0 + 8) * LDA + k0 + tig];
            float a2f = sA[r0 * LDA + k0 + tig + 4];
            float a3f = sA[(r0 + 8) * LDA + k0 + tig + 4];
            uint32_t ah[4], al[4];
            split_tf32(a0f, ah[0], al[0]);
            split_tf32(a1f, ah[1], al[1]);
            split_tf32(a2f, ah[2], al[2]);
            split_tf32(a3f, ah[3], al[3]);
#pragma unroll
            for (int nt = 0; nt < 4; nt++) {
                mma_tf32(acc[mt][nt], ah, bh[nt]);
                mma_tf32(acc[mt][nt], ah, bl[nt]);
                mma_tf32(acc[mt][nt], al, bh[nt]);
            }
        }
    }

#pragma unroll
    for (int mt = 0; mt < 2; mt++) {
#pragma unroll
        for (int nt = 0; nt < 4; nt++) {
            int r = row0 + mbase + mt * 16 + gid;
            int c = nbase + nt * 8 + 2 * tig;
            if (r < N)
                *(float2*)&C[(size_t)r * 128 + c] =
                    make_float2(acc[mt][nt][0], acc[mt][nt][1]);
            if (r + 8 < N)
                *(float2*)&C[(size_t)(r + 8) * 128 + c] =
                    make_float2(acc[mt][nt][2], acc[mt][nt][3]);
        }
    }
}

// ---------------------------------------------------------------------------
// Gather-side aggregation (atomic-free): one warp per node.
template <int POOL>
__global__ void k_agg(const float* __restrict__ gm, const float* __restrict__ bias,
                      float* __restrict__ outb, const int* __restrict__ batch, int N) {
    int n = (blockIdx.x * blockDim.x + threadIdx.x) >> 5;
    int lane = threadIdx.x & 31;
    if (n >= N) return;

    float selfw = g_dis[n];
    selfw *= selfw;
    const float4* gm4 = (const float4*)gm;
    float4 acc = gm4[(size_t)n * 32 + lane];
    acc.x *= selfw; acc.y *= selfw; acc.z *= selfw; acc.w *= selfw;

    int beg = g_rowptr[n], end = g_rowptr[n + 1];
    for (int e = beg; e < end; e++) {
        int s = g_csr_src[e];
        float wn = g_csr_nrm[e];
        float4 v = gm4[(size_t)s * 32 + lane];
        acc.x += v.x * wn;
        acc.y += v.y * wn;
        acc.z += v.z * wn;
        acc.w += v.w * wn;
    }

    float4 b = ((const float4*)bias)[lane];
    acc.x = fmaxf(acc.x + b.x, 0.f);
    acc.y = fmaxf(acc.y + b.y, 0.f);
    acc.z = fmaxf(acc.z + b.z, 0.f);
    acc.w = fmaxf(acc.w + b.w, 0.f);

    if (POOL) {
        int g = batch[n];
        float* p = g_pool + (size_t)g * 128 + lane * 4;
        atomicAdd(p + 0, acc.x);
        atomicAdd(p + 1, acc.y);
        atomicAdd(p + 2, acc.z);
        atomicAdd(p + 3, acc.w);
    } else {
        ((float4*)outb)[(size_t)n * 32 + lane] = acc;
    }
}

// final: out[g] = (pool[g]/cnt[g]) . Wfc + bfc
__global__ void k_final(const float* __restrict__ Wfc, const float* __restrict__ bfc,
                        float* __restrict__ out, int G) {
    int g = blockIdx.x;
    int t = threadIdx.x;           // 128 threads
    float c = fmaxf(g_cnt[g], 1.0f);
    float val = (g_pool[(size_t)g * 128 + t] / c) * Wfc[t];
#pragma unroll
    for (int o = 16; o > 0; o >>= 1) val += __shfl_down_sync(0xffffffffu, val, o);
    __shared__ float sred[4];
    int w = t >> 5;
    if ((t & 31) == 0) sred[w] = val;
    __syncthreads();
    if (t == 0) out[g] = sred[0] + sred[1] + sred[2] + sred[3] + bfc[0];
}

// ---------------------------------------------------------------------------
extern "C" void kernel_launch(void* const* d_in, const int* in_sizes, int n_in,
                              void* d_out, int out_size) {
    const float* x     = (const float*)d_in[0];
    const int*   ei    = (const int*)d_in[1];    // int32 in harness
    const int*   batch = (const int*)d_in[2];    // int32 in harness
    const float* W1    = (const float*)d_in[3];
    const float* b1    = (const float*)d_in[4];
    const float* W2    = (const float*)d_in[5];
    const float* b2    = (const float*)d_in[6];
    const float* Wfc   = (const float*)d_in[7];
    const float* bfc   = (const float*)d_in[8];
    float* out = (float*)d_out;

    int N = in_sizes[0] / HDIM;
    int E = in_sizes[1] / 2;
    int G = out_size;

    float *buf1, *buf2;
    cudaGetSymbolAddress((void**)&buf1, g_buf1);
    cudaGetSymbolAddress((void**)&buf2, g_buf2);

    size_t gsmem = (size_t)(128 * LDW + MBLK * LDA) * sizeof(float);   // ~101 KB
    cudaFuncSetAttribute(k_gemm_tf32, cudaFuncAttributeMaxDynamicSharedMemorySize,
                         (int)gsmem);

    int initN = N > G * HDIM ? N : G * HDIM;
    int nblk = (N + SCAN_BLK - 1) / SCAN_BLK;

    int gemmGrid = (N + MBLK - 1) / MBLK;
    int aggBlocks = (N * 32 + 255) / 256;

    // Profiler snapshots the 4th launch -> k_scan_c there to verify its fix.
    k_init<<<(initN + 255) / 256, 256>>>(N, G);                 // 1
    k_edges<<<(E + 255) / 256, 256>>>(ei, E);                   // 2
    k_scan_a<<<nblk, 256>>>(N);                                 // 3
    k_scan_c<<<nblk, 256>>>(batch, N, E, nblk);                 // 4  <- profiled
    k_gemm_tf32<<<gemmGrid, 256, gsmem>>>(x, W1, buf1, N);      // 5
    k_fill<<<(E + 255) / 256, 256>>>(ei, E);                    // 6

    // ---- layer 1 aggregation ----
    k_agg<0><<<aggBlocks, 256>>>(buf1, b1, buf2, batch, N);     // 7

    // ---- layer 2 (pool fused into aggregation epilogue) ----
    k_gemm_tf32<<<gemmGrid, 256, gsmem>>>(buf2, W2, buf1, N);   // 8
    k_agg<1><<<aggBlocks, 256>>>(buf1, b2, nullptr, batch, N);  // 9

    // ---- readout ----
    k_final<<<G, 128>>>(Wfc, bfc, out, G);                      // 10
}

// round 15
// speedup vs baseline: 1.2842x; 1.0218x over previous
#include <cuda_runtime.h>
#include <cstdint>

// Problem shapes (fixed by the dataset)
#define NMAX 100000
#define EMAX 600000
#define HDIM 128
#define GMAXX 512
#define SCAN_BLK 2048          // 256 threads x 8 elems

#define LDA 132                // A-tile smem stride (pad 4: conflict-free A frags)
#define LDW 136                // W-tile smem stride (pad 8: conflict-free B frags)
#define MBLK 64                // GEMM rows per block (2 blocks/SM)

// Scratch (allocation-free rule: __device__ globals)
__device__ float g_buf1[(size_t)NMAX * HDIM];   // GEMM outputs
__device__ float g_buf2[(size_t)NMAX * HDIM];   // hidden after layer 1
__device__ int   g_ideg[NMAX];                  // in-degree (excl. self loop)
__device__ float g_dis[NMAX];                   // rsqrt(deg+1)
__device__ int   g_rowptr[NMAX + 1];
__device__ int   g_cursor[NMAX];
__device__ int   g_csr_src[EMAX];
__device__ float g_csr_nrm[EMAX];
__device__ int   g_blk[128];                    // scan block sums
__device__ float g_pool[(size_t)GMAXX * HDIM];
__device__ int   g_gstart[GMAXX];               // per-graph node range (sorted batch)
__device__ int   g_gend[GMAXX];

// ---------------------------------------------------------------------------
__global__ void k_init(int N, int G) {
    int i = blockIdx.x * blockDim.x + threadIdx.x;
    if (i < N) g_ideg[i] = 0;
    if (i < G * HDIM) g_pool[i] = 0.0f;
    if (i < G) { g_gstart[i] = 0; g_gend[i] = 0; }
}

// degree histogram only
__global__ void k_edges(const int* __restrict__ ei, int E) {
    int i = blockIdx.x * blockDim.x + threadIdx.x;
    if (i >= E) return;
    atomicAdd(&g_ideg[ei[(size_t)E + i]], 1);
}

// ---- exclusive scan of g_ideg -> g_rowptr ----
__global__ void k_scan_a(int N) {           // per-block sums
    int b = blockIdx.x, t = threadIdx.x;
    int base = b * SCAN_BLK + t * 8;
    int s = 0;
#pragma unroll
    for (int j = 0; j < 8; j++) { int i = base + j; s += (i < N) ? g_ideg[i] : 0; }
#pragma unroll
    for (int o = 16; o > 0; o >>= 1) s += __shfl_down_sync(0xffffffffu, s, o);
    __shared__ int wt[8];
    if ((t & 31) == 0) wt[t >> 5] = s;
    __syncthreads();
    if (t == 0) {
        int acc = 0;
        for (int i = 0; i < 8; i++) acc += wt[i];
        g_blk[b] = acc;
    }
}

// scan pass 2 + per-node derived data. NO g_cnt atomics: R14 profile showed
// the 100K fp32 atomicAdds onto 512 sorted (=maximally contended) counters
// were the 18.8us. Sorted batch -> counts are segment boundaries instead.
__global__ void k_scan_c(const int* __restrict__ batch, int N, int E, int nblk) {
    int b = blockIdx.x, t = threadIdx.x;
    __shared__ int sblk[128];
    __shared__ int blkoff;
    if (t < 128) sblk[t] = (t < nblk) ? g_blk[t] : 0;
    __syncthreads();
    if (t == 0) {
        int acc = 0;
        for (int i = 0; i < b; i++) acc += sblk[i];
        blkoff = acc;
    }
    int base = b * SCAN_BLK + t * 8;
    int pre[8];
    int s = 0;
#pragma unroll
    for (int j = 0; j < 8; j++) {
        int i = base + j;
        int v = (i < N) ? g_ideg[i] : 0;
        pre[j] = s; s += v;
    }
    int lane = t & 31, w = t >> 5;
    int incl = s;
#pragma unroll
    for (int o = 1; o < 32; o <<= 1) {
        int x = __shfl_up_sync(0xffffffffu, incl, o);
        if (lane >= o) incl += x;
    }
    __shared__ int wt[8], wb[8];
    if (lane == 31) wt[w] = incl;
    __syncthreads();
    if (t == 0) {
        int acc = 0;
        for (int i = 0; i < 8; i++) { wb[i] = acc; acc += wt[i]; }
    }
    __syncthreads();
    int thr_excl = wb[w] + incl - s;
    int gbase = blkoff + thr_excl;
#pragma unroll
    for (int j = 0; j < 8; j++) {
        int i = base + j;
        if (i < N) {
            int rp = gbase + pre[j];
            g_rowptr[i] = rp;
            g_cursor[i] = rp;
            g_dis[i] = rsqrtf((float)(g_ideg[i] + 1));
            // graph segment boundaries (plain stores, <=2*G total across grid)
            int bg = batch[i];
            if (i == 0 || batch[i - 1] != bg) g_gstart[bg] = i;
            if (i == N - 1 || batch[i + 1] != bg) g_gend[bg] = i + 1;
        }
    }
    if (b == 0 && t == 0) g_rowptr[N] = E;
}

// fill CSR buckets straight from ei
__global__ void k_fill(const int* __restrict__ ei, int E) {
    int e = blockIdx.x * blockDim.x + threadIdx.x;
    if (e >= E) return;
    int s = ei[e];
    int d = ei[(size_t)E + e];
    int pos = atomicAdd(&g_cursor[d], 1);
    g_csr_src[pos] = s;
    g_csr_nrm[pos] = g_dis[s] * g_dis[d];
}

// ---------------------------------------------------------------------------
// 3xTF32 GEMM: C[N,128] = A[N,128] @ W[128,128], fp32-grade accuracy.
__device__ __forceinline__ uint32_t f2tf32(float x) {
    uint32_t r;
    asm("cvt.rna.tf32.f32 %0, %1;" : "=r"(r) : "f"(x));
    return r;
}
__device__ __forceinline__ void split_tf32(float x, uint32_t& hi, uint32_t& lo) {
    hi = f2tf32(x);
    lo = f2tf32(x - __uint_as_float(hi));
}
__device__ __forceinline__ void mma_tf32(float* c, const uint32_t* a, const uint32_t* b) {
    asm volatile(
        "mma.sync.aligned.m16n8k8.row.col.f32.tf32.tf32.f32 "
        "{%0,%1,%2,%3}, {%4,%5,%6,%7}, {%8,%9}, {%0,%1,%2,%3};"
        : "+f"(c[0]), "+f"(c[1]), "+f"(c[2]), "+f"(c[3])
        : "r"(a[0]), "r"(a[1]), "r"(a[2]), "r"(a[3]), "r"(b[0]), "r"(b[1]));
}

__global__ void __launch_bounds__(256, 2)
k_gemm_tf32(const float* __restrict__ A, const float* __restrict__ Wm,
            float* __restrict__ C, int N) {
    extern __shared__ float sh[];
    float* sW = sh;                   // 128 x LDW
    float* sA = sh + 128 * LDW;       // MBLK x LDA
    int tid = threadIdx.x;
    int row0 = blockIdx.x * MBLK;

    const float4* W4 = (const float4*)Wm;
    const float4* A4 = (const float4*)A;
#pragma unroll
    for (int i = 0; i < 16; i++) {
        int idx = tid + 256 * i;       // 0..4095
        int r = idx >> 5;              // 0..127
        int c4 = idx & 31;
        *(float4*)&sW[r * LDW + c4 * 4] = W4[idx];
    }
#pragma unroll
    for (int i = 0; i < 8; i++) {
        int idx = tid + 256 * i;       // 0..2047
        int r = idx >> 5;              // 0..63
        int c4 = idx & 31;
        float4 v = make_float4(0.f, 0.f, 0.f, 0.f);
        if (row0 + r < N) v = A4[(size_t)(row0 + r) * 32 + c4];
        *(float4*)&sA[r * LDA + c4 * 4] = v;
    }
    __syncthreads();

    int wid = tid >> 5, lane = tid & 31;
    int gid = lane >> 2, tig = lane & 3;
    int mbase = (wid >> 2) * 32;       // warp_m in {0,1}
    int nbase = (wid & 3) * 32;        // warp_n in {0..3}

    float acc[2][4][4];
#pragma unroll
    for (int i = 0; i < 2; i++)
#pragma unroll
        for (int j = 0; j < 4; j++)
#pragma unroll
            for (int r = 0; r < 4; r++) acc[i][j][r] = 0.f;

#pragma unroll
    for (int kt = 0; kt < 16; kt++) {
        int k0 = kt * 8;
        uint32_t bh[4][2], bl[4][2];
#pragma unroll
        for (int nt = 0; nt < 4; nt++) {
            int ncol = nbase + nt * 8 + gid;
            float b0f = sW[(k0 + tig) * LDW + ncol];
            float b1f = sW[(k0 + tig + 4) * LDW + ncol];
            split_tf32(b0f, bh[nt][0], bl[nt][0]);
            split_tf32(b1f, bh[nt][1], bl[nt][1]);
        }
#pragma unroll
        for (int mt = 0; mt < 2; mt++) {
            int r0 = mbase + mt * 16 + gid;
            float a0f = sA[r0 * LDA + k0 + tig];
            float a1f = sA[(r0 + 8) * LDA + k0 + tig];
            float a2f = sA[r0 * LDA + k0 + tig + 4];
            float a3f = sA[(r0 + 8) * LDA + k0 + tig + 4];
            uint32_t ah[4], al[4];
            split_tf32(a0f, ah[0], al[0]);
            split_tf32(a1f, ah[1], al[1]);
            split_tf32(a2f, ah[2], al[2]);
            split_tf32(a3f, ah[3], al[3]);
#pragma unroll
            for (int nt = 0; nt < 4; nt++) {
                mma_tf32(acc[mt][nt], ah, bh[nt]);
                mma_tf32(acc[mt][nt], ah, bl[nt]);
                mma_tf32(acc[mt][nt], al, bh[nt]);
            }
        }
    }

#pragma unroll
    for (int mt = 0; mt < 2; mt++) {
#pragma unroll
        for (int nt = 0; nt < 4; nt++) {
            int r = row0 + mbase + mt * 16 + gid;
            int c = nbase + nt * 8 + 2 * tig;
            if (r < N)
                *(float2*)&C[(size_t)r * 128 + c] =
                    make_float2(acc[mt][nt][0], acc[mt][nt][1]);
            if (r + 8 < N)
                *(float2*)&C[(size_t)(r + 8) * 128 + c] =
                    make_float2(acc[mt][nt][2], acc[mt][nt][3]);
        }
    }
}

// ---------------------------------------------------------------------------
// Gather-side aggregation (atomic-free): one warp per node.
template <int POOL>
__global__ void k_agg(const float* __restrict__ gm, const float* __restrict__ bias,
                      float* __restrict__ outb, const int* __restrict__ batch, int N) {
    int n = (blockIdx.x * blockDim.x + threadIdx.x) >> 5;
    int lane = threadIdx.x & 31;
    if (n >= N) return;

    float selfw = g_dis[n];
    selfw *= selfw;
    const float4* gm4 = (const float4*)gm;
    float4 acc = gm4[(size_t)n * 32 + lane];
    acc.x *= selfw; acc.y *= selfw; acc.z *= selfw; acc.w *= selfw;

    int beg = g_rowptr[n], end = g_rowptr[n + 1];
    for (int e = beg; e < end; e++) {
        int s = g_csr_src[e];
        float wn = g_csr_nrm[e];
        float4 v = gm4[(size_t)s * 32 + lane];
        acc.x += v.x * wn;
        acc.y += v.y * wn;
        acc.z += v.z * wn;
        acc.w += v.w * wn;
    }

    float4 b = ((const float4*)bias)[lane];
    acc.x = fmaxf(acc.x + b.x, 0.f);
    acc.y = fmaxf(acc.y + b.y, 0.f);
    acc.z = fmaxf(acc.z + b.z, 0.f);
    acc.w = fmaxf(acc.w + b.w, 0.f);

    if (POOL) {
        int g = batch[n];
        float* p = g_pool + (size_t)g * 128 + lane * 4;
        atomicAdd(p + 0, acc.x);
        atomicAdd(p + 1, acc.y);
        atomicAdd(p + 2, acc.z);
        atomicAdd(p + 3, acc.w);
    } else {
        ((float4*)outb)[(size_t)n * 32 + lane] = acc;
    }
}

// final: out[g] = (pool[g]/cnt[g]) . Wfc + bfc ; cnt from segment boundaries
__global__ void k_final(const float* __restrict__ Wfc, const float* __restrict__ bfc,
                        float* __restrict__ out, int G) {
    int g = blockIdx.x;
    int t = threadIdx.x;           // 128 threads
    float c = fmaxf((float)(g_gend[g] - g_gstart[g]), 1.0f);
    float val = (g_pool[(size_t)g * 128 + t] / c) * Wfc[t];
#pragma unroll
    for (int o = 16; o > 0; o >>= 1) val += __shfl_down_sync(0xffffffffu, val, o);
    __shared__ float sred[4];
    int w = t >> 5;
    if ((t & 31) == 0) sred[w] = val;
    __syncthreads();
    if (t == 0) out[g] = sred[0] + sred[1] + sred[2] + sred[3] + bfc[0];
}

// ---------------------------------------------------------------------------
extern "C" void kernel_launch(void* const* d_in, const int* in_sizes, int n_in,
                              void* d_out, int out_size) {
    const float* x     = (const float*)d_in[0];
    const int*   ei    = (const int*)d_in[1];    // int32 in harness
    const int*   batch = (const int*)d_in[2];    // int32 in harness
    const float* W1    = (const float*)d_in[3];
    const float* b1    = (const float*)d_in[4];
    const float* W2    = (const float*)d_in[5];
    const float* b2    = (const float*)d_in[6];
    const float* Wfc   = (const float*)d_in[7];
    const float* bfc   = (const float*)d_in[8];
    float* out = (float*)d_out;

    int N = in_sizes[0] / HDIM;
    int E = in_sizes[1] / 2;
    int G = out_size;

    float *buf1, *buf2;
    cudaGetSymbolAddress((void**)&buf1, g_buf1);
    cudaGetSymbolAddress((void**)&buf2, g_buf2);

    size_t gsmem = (size_t)(128 * LDW + MBLK * LDA) * sizeof(float);   // ~101 KB
    cudaFuncSetAttribute(k_gemm_tf32, cudaFuncAttributeMaxDynamicSharedMemorySize,
                         (int)gsmem);

    int initN = N > G * HDIM ? N : G * HDIM;
    int nblk = (N + SCAN_BLK - 1) / SCAN_BLK;

    int gemmGrid = (N + MBLK - 1) / MBLK;
    int aggBlocks = (N * 32 + 255) / 256;

    // Profiler snapshots the 4th launch -> k_scan_c there to verify atomic fix.
    k_init<<<(initN + 255) / 256, 256>>>(N, G);                 // 1
    k_edges<<<(E + 255) / 256, 256>>>(ei, E);                   // 2
    k_scan_a<<<nblk, 256>>>(N);                                 // 3
    k_scan_c<<<nblk, 256>>>(batch, N, E, nblk);                 // 4  <- profiled
    k_gemm_tf32<<<gemmGrid, 256, gsmem>>>(x, W1, buf1, N);      // 5
    k_fill<<<(E + 255) / 256, 256>>>(ei, E);                    // 6

    // ---- layer 1 aggregation ----
    k_agg<0><<<aggBlocks, 256>>>(buf1, b1, buf2, batch, N);     // 7

    // ---- layer 2 (pool fused into aggregation epilogue) ----
    k_gemm_tf32<<<gemmGrid, 256, gsmem>>>(buf2, W2, buf1, N);   // 8
    k_agg<1><<<aggBlocks, 256>>>(buf1, b2, nullptr, batch, N);  // 9

    // ---- readout ----
    k_final<<<G, 128>>>(Wfc, bfc, out, G);                      // 10
}

// round 16
// speedup vs baseline: 1.3905x; 1.0828x over previous
#include <cuda_runtime.h>
#include <cstdint>

// Problem shapes (fixed by the dataset)
#define NMAX 100000
#define EMAX 600000
#define HDIM 128
#define GMAXX 512
#define SCAN_BLK 2048          // 256 threads x 8 elems

#define LDA 132                // A-tile smem stride (pad 4: conflict-free A frags)
#define MBLK 64                // GEMM rows per block (2 blocks/SM)

// Scratch (allocation-free rule: __device__ globals)
__device__ float g_buf1[(size_t)NMAX * HDIM];   // GEMM outputs
__device__ float g_buf2[(size_t)NMAX * HDIM];   // hidden after layer 1
__device__ int   g_ideg[NMAX];                  // in-degree (excl. self loop)
__device__ float g_dis[NMAX];                   // rsqrt(deg+1)
__device__ int   g_rowptr[NMAX + 1];
__device__ int   g_cursor[NMAX];
__device__ int   g_csr_src[EMAX];
__device__ float g_csr_nrm[EMAX];
__device__ int   g_blk[128];                    // scan block sums
__device__ float g_pool[(size_t)GMAXX * HDIM];
__device__ int   g_gstart[GMAXX];               // per-graph node range (sorted batch)
__device__ int   g_gend[GMAXX];
// Pre-split B fragments: [nb(4)][kt(16)][nt(4)][lane(32)] uint4 = 32KB each
__device__ uint4 g_fragA[4 * 16 * 4 * 32];
__device__ uint4 g_fragB[4 * 16 * 4 * 32];

// ---------------------------------------------------------------------------
__global__ void k_init(int N, int G) {
    int i = blockIdx.x * blockDim.x + threadIdx.x;
    if (i < N) g_ideg[i] = 0;
    if (i < G * HDIM) g_pool[i] = 0.0f;
    if (i < G) { g_gstart[i] = 0; g_gend[i] = 0; }
}

// degree histogram only
__global__ void k_edges(const int* __restrict__ ei, int E) {
    int i = blockIdx.x * blockDim.x + threadIdx.x;
    if (i >= E) return;
    atomicAdd(&g_ideg[ei[(size_t)E + i]], 1);
}

// ---- exclusive scan of g_ideg -> g_rowptr ----
__global__ void k_scan_a(int N) {           // per-block sums
    int b = blockIdx.x, t = threadIdx.x;
    int base = b * SCAN_BLK + t * 8;
    int s = 0;
#pragma unroll
    for (int j = 0; j < 8; j++) { int i = base + j; s += (i < N) ? g_ideg[i] : 0; }
#pragma unroll
    for (int o = 16; o > 0; o >>= 1) s += __shfl_down_sync(0xffffffffu, s, o);
    __shared__ int wt[8];
    if ((t & 31) == 0) wt[t >> 5] = s;
    __syncthreads();
    if (t == 0) {
        int acc = 0;
        for (int i = 0; i < 8; i++) acc += wt[i];
        g_blk[b] = acc;
    }
}

// scan pass 2 + per-node derived data (boundary stores, no counter atomics)
__global__ void k_scan_c(const int* __restrict__ batch, int N, int E, int nblk) {
    int b = blockIdx.x, t = threadIdx.x;
    __shared__ int sblk[128];
    __shared__ int blkoff;
    if (t < 128) sblk[t] = (t < nblk) ? g_blk[t] : 0;
    __syncthreads();
    if (t == 0) {
        int acc = 0;
        for (int i = 0; i < b; i++) acc += sblk[i];
        blkoff = acc;
    }
    int base = b * SCAN_BLK + t * 8;
    int pre[8];
    int s = 0;
#pragma unroll
    for (int j = 0; j < 8; j++) {
        int i = base + j;
        int v = (i < N) ? g_ideg[i] : 0;
        pre[j] = s; s += v;
    }
    int lane = t & 31, w = t >> 5;
    int incl = s;
#pragma unroll
    for (int o = 1; o < 32; o <<= 1) {
        int x = __shfl_up_sync(0xffffffffu, incl, o);
        if (lane >= o) incl += x;
    }
    __shared__ int wt[8], wb[8];
    if (lane == 31) wt[w] = incl;
    __syncthreads();
    if (t == 0) {
        int acc = 0;
        for (int i = 0; i < 8; i++) { wb[i] = acc; acc += wt[i]; }
    }
    __syncthreads();
    int thr_excl = wb[w] + incl - s;
    int gbase = blkoff + thr_excl;
#pragma unroll
    for (int j = 0; j < 8; j++) {
        int i = base + j;
        if (i < N) {
            int rp = gbase + pre[j];
            g_rowptr[i] = rp;
            g_cursor[i] = rp;
            g_dis[i] = rsqrtf((float)(g_ideg[i] + 1));
            int bg = batch[i];
            if (i == 0 || batch[i - 1] != bg) g_gstart[bg] = i;
            if (i == N - 1 || batch[i + 1] != bg) g_gend[bg] = i + 1;
        }
    }
    if (b == 0 && t == 0) g_rowptr[N] = E;
}

// fill CSR buckets straight from ei
__global__ void k_fill(const int* __restrict__ ei, int E) {
    int e = blockIdx.x * blockDim.x + threadIdx.x;
    if (e >= E) return;
    int s = ei[e];
    int d = ei[(size_t)E + e];
    int pos = atomicAdd(&g_cursor[d], 1);
    g_csr_src[pos] = s;
    g_csr_nrm[pos] = g_dis[s] * g_dis[d];
}

// ---------------------------------------------------------------------------
// tf32 helpers
__device__ __forceinline__ uint32_t f2tf32(float x) {
    uint32_t r;
    asm("cvt.rna.tf32.f32 %0, %1;" : "=r"(r) : "f"(x));
    return r;
}
__device__ __forceinline__ void split_tf32(float x, uint32_t& hi, uint32_t& lo) {
    hi = f2tf32(x);
    lo = f2tf32(x - __uint_as_float(hi));
}
__device__ __forceinline__ void mma_tf32(float* c, const uint32_t* a, const uint32_t* b) {
    asm volatile(
        "mma.sync.aligned.m16n8k8.row.col.f32.tf32.tf32.f32 "
        "{%0,%1,%2,%3}, {%4,%5,%6,%7}, {%8,%9}, {%0,%1,%2,%3};"
        : "+f"(c[0]), "+f"(c[1]), "+f"(c[2]), "+f"(c[3])
        : "r"(a[0]), "r"(a[1]), "r"(a[2]), "r"(a[3]), "r"(b[0]), "r"(b[1]));
}

// Pre-split W into MMA-ready B fragments (hi/lo), once per layer.
// Every GEMM block previously re-split identical W data (24 ALU instrs per
// k-step per thread, 1563x redundant) -> R12 profile alu=36.9% vs tensor=49.1%.
// Layout: [nb][kt][nt][lane] -> uint4{bh0, bh1, bl0, bl1}
__global__ void k_wsplit(const float* __restrict__ Wm, uint4* __restrict__ frag) {
    int idx = blockIdx.x * blockDim.x + threadIdx.x;   // 0..8191
    if (idx >= 4 * 16 * 4 * 32) return;
    int lane = idx & 31;
    int nt   = (idx >> 5) & 3;
    int kt   = (idx >> 7) & 15;
    int nb   = idx >> 11;
    int gid = lane >> 2, tig = lane & 3;
    int ncol = nb * 32 + nt * 8 + gid;
    int k0 = kt * 8;
    float b0 = Wm[(k0 + tig) * 128 + ncol];
    float b1 = Wm[(k0 + tig + 4) * 128 + ncol];
    uint32_t h0, l0, h1, l1;
    split_tf32(b0, h0, l0);
    split_tf32(b1, h1, l1);
    frag[idx] = make_uint4(h0, h1, l0, l1);
}

// 3xTF32 GEMM with pre-split B fragments (L1-resident LDG.128 per k-step).
// smem = A tile only (~34 KB); W smem tile + in-loop B splits eliminated.
__global__ void __launch_bounds__(256, 2)
k_gemm_tf32(const float* __restrict__ A, const uint4* __restrict__ frag,
            float* __restrict__ C, int N) {
    extern __shared__ float sh[];
    float* sA = sh;                   // MBLK x LDA
    int tid = threadIdx.x;
    int row0 = blockIdx.x * MBLK;

    const float4* A4 = (const float4*)A;
#pragma unroll
    for (int i = 0; i < 8; i++) {
        int idx = tid + 256 * i;       // 0..2047
        int r = idx >> 5;              // 0..63
        int c4 = idx & 31;
        float4 v = make_float4(0.f, 0.f, 0.f, 0.f);
        if (row0 + r < N) v = A4[(size_t)(row0 + r) * 32 + c4];
        *(float4*)&sA[r * LDA + c4 * 4] = v;
    }
    __syncthreads();

    int wid = tid >> 5, lane = tid & 31;
    int gid = lane >> 2, tig = lane & 3;
    int mbase = (wid >> 2) * 32;       // warp_m in {0,1}
    int nb = wid & 3;                  // warp_n in {0..3}
    int nbase = nb * 32;

    // fragment base for this warp: [nb][kt=0][nt=0][lane]
    const uint4* fbase = frag + ((size_t)nb << 11) + lane;

    float acc[2][4][4];
#pragma unroll
    for (int i = 0; i < 2; i++)
#pragma unroll
        for (int j = 0; j < 4; j++)
#pragma unroll
            for (int r = 0; r < 4; r++) acc[i][j][r] = 0.f;

#pragma unroll
    for (int kt = 0; kt < 16; kt++) {
        int k0 = kt * 8;
        uint4 f[4];
#pragma unroll
        for (int nt = 0; nt < 4; nt++)
            f[nt] = fbase[(kt * 4 + nt) * 32];
#pragma unroll
        for (int mt = 0; mt < 2; mt++) {
            int r0 = mbase + mt * 16 + gid;
            float a0f = sA[r0 * LDA + k0 + tig];
            float a1f = sA[(r0 + 8) * LDA + k0 + tig];
            float a2f = sA[r0 * LDA + k0 + tig + 4];
            float a3f = sA[(r0 + 8) * LDA + k0 + tig + 4];
            uint32_t ah[4], al[4];
            split_tf32(a0f, ah[0], al[0]);
            split_tf32(a1f, ah[1], al[1]);
            split_tf32(a2f, ah[2], al[2]);
            split_tf32(a3f, ah[3], al[3]);
#pragma unroll
            for (int nt = 0; nt < 4; nt++) {
                uint32_t bh[2] = { f[nt].x, f[nt].y };
                uint32_t bl[2] = { f[nt].z, f[nt].w };
                mma_tf32(acc[mt][nt], ah, bh);
                mma_tf32(acc[mt][nt], ah, bl);
                mma_tf32(acc[mt][nt], al, bh);
            }
        }
    }

#pragma unroll
    for (int mt = 0; mt < 2; mt++) {
#pragma unroll
        for (int nt = 0; nt < 4; nt++) {
            int r = row0 + mbase + mt * 16 + gid;
            int c = nbase + nt * 8 + 2 * tig;
            if (r < N)
                *(float2*)&C[(size_t)r * 128 + c] =
                    make_float2(acc[mt][nt][0], acc[mt][nt][1]);
            if (r + 8 < N)
                *(float2*)&C[(size_t)(r + 8) * 128 + c] =
                    make_float2(acc[mt][nt][2], acc[mt][nt][3]);
        }
    }
}

// ---------------------------------------------------------------------------
// Gather-side aggregation (atomic-free): one warp per node.
template <int POOL>
__global__ void k_agg(const float* __restrict__ gm, const float* __restrict__ bias,
                      float* __restrict__ outb, const int* __restrict__ batch, int N) {
    int n = (blockIdx.x * blockDim.x + threadIdx.x) >> 5;
    int lane = threadIdx.x & 31;
    if (n >= N) return;

    float selfw = g_dis[n];
    selfw *= selfw;
    const float4* gm4 = (const float4*)gm;
    float4 acc = gm4[(size_t)n * 32 + lane];
    acc.x *= selfw; acc.y *= selfw; acc.z *= selfw; acc.w *= selfw;

    int beg = g_rowptr[n], end = g_rowptr[n + 1];
    for (int e = beg; e < end; e++) {
        int s = g_csr_src[e];
        float wn = g_csr_nrm[e];
        float4 v = gm4[(size_t)s * 32 + lane];
        acc.x += v.x * wn;
        acc.y += v.y * wn;
        acc.z += v.z * wn;
        acc.w += v.w * wn;
    }

    float4 b = ((const float4*)bias)[lane];
    acc.x = fmaxf(acc.x + b.x, 0.f);
    acc.y = fmaxf(acc.y + b.y, 0.f);
    acc.z = fmaxf(acc.z + b.z, 0.f);
    acc.w = fmaxf(acc.w + b.w, 0.f);

    if (POOL) {
        int g = batch[n];
        float* p = g_pool + (size_t)g * 128 + lane * 4;
        atomicAdd(p + 0, acc.x);
        atomicAdd(p + 1, acc.y);
        atomicAdd(p + 2, acc.z);
        atomicAdd(p + 3, acc.w);
    } else {
        ((float4*)outb)[(size_t)n * 32 + lane] = acc;
    }
}

// final: out[g] = (pool[g]/cnt[g]) . Wfc + bfc ; cnt from segment boundaries
__global__ void k_final(const float* __restrict__ Wfc, const float* __restrict__ bfc,
                        float* __restrict__ out, int G) {
    int g = blockIdx.x;
    int t = threadIdx.x;           // 128 threads
    float c = fmaxf((float)(g_gend[g] - g_gstart[g]), 1.0f);
    float val = (g_pool[(size_t)g * 128 + t] / c) * Wfc[t];
#pragma unroll
    for (int o = 16; o > 0; o >>= 1) val += __shfl_down_sync(0xffffffffu, val, o);
    __shared__ float sred[4];
    int w = t >> 5;
    if ((t & 31) == 0) sred[w] = val;
    __syncthreads();
    if (t == 0) out[g] = sred[0] + sred[1] + sred[2] + sred[3] + bfc[0];
}

// ---------------------------------------------------------------------------
extern "C" void kernel_launch(void* const* d_in, const int* in_sizes, int n_in,
                              void* d_out, int out_size) {
    const float* x     = (const float*)d_in[0];
    const int*   ei    = (const int*)d_in[1];    // int32 in harness
    const int*   batch = (const int*)d_in[2];    // int32 in harness
    const float* W1    = (const float*)d_in[3];
    const float* b1    = (const float*)d_in[4];
    const float* W2    = (const float*)d_in[5];
    const float* b2    = (const float*)d_in[6];
    const float* Wfc   = (const float*)d_in[7];
    const float* bfc   = (const float*)d_in[8];
    float* out = (float*)d_out;

    int N = in_sizes[0] / HDIM;
    int E = in_sizes[1] / 2;
    int G = out_size;

    float *buf1, *buf2;
    uint4 *fragA, *fragB;
    cudaGetSymbolAddress((void**)&buf1, g_buf1);
    cudaGetSymbolAddress((void**)&buf2, g_buf2);
    cudaGetSymbolAddress((void**)&fragA, g_fragA);
    cudaGetSymbolAddress((void**)&fragB, g_fragB);

    size_t gsmem = (size_t)(MBLK * LDA) * sizeof(float);   // ~34 KB (A tile only)
    cudaFuncSetAttribute(k_gemm_tf32, cudaFuncAttributeMaxDynamicSharedMemorySize,
                         (int)gsmem);

    int initN = N > G * HDIM ? N : G * HDIM;
    int nblk = (N + SCAN_BLK - 1) / SCAN_BLK;

    int gemmGrid = (N + MBLK - 1) / MBLK;
    int aggBlocks = (N * 32 + 255) / 256;

    // Profiler snapshots the 4th launch -> layer-1 GEMM there.
    k_init<<<(initN + 255) / 256, 256>>>(N, G);                  // 1
    k_edges<<<(E + 255) / 256, 256>>>(ei, E);                    // 2
    k_wsplit<<<32, 256>>>(W1, fragA);                            // 3
    k_gemm_tf32<<<gemmGrid, 256, gsmem>>>(x, fragA, buf1, N);    // 4  <- profiled
    k_scan_a<<<nblk, 256>>>(N);                                  // 5
    k_scan_c<<<nblk, 256>>>(batch, N, E, nblk);                  // 6
    k_fill<<<(E + 255) / 256, 256>>>(ei, E);                     // 7

    // ---- layer 1 aggregation ----
    k_agg<0><<<aggBlocks, 256>>>(buf1, b1, buf2, batch, N);      // 8

    // ---- layer 2 (pool fused into aggregation epilogue) ----
    k_wsplit<<<32, 256>>>(W2, fragB);                            // 9
    k_gemm_tf32<<<gemmGrid, 256, gsmem>>>(buf2, fragB, buf1, N); // 10
    k_agg<1><<<aggBlocks, 256>>>(buf1, b2, nullptr, batch, N);   // 11

    // ---- readout ----
    k_final<<<G, 128>>>(Wfc, bfc, out, G);                       // 12
}